// round 5
// baseline (speedup 1.0000x reference)
#include <cuda_runtime.h>
#include <cuda_bf16.h>
#include <cstdint>
#include <math.h>

#define B_ 2
#define S_ 2048
#define E_ 2048
#define H_ 32
#define D_ 64
#define M_ (B_*S_)
#define SCALE_ 0.125f

// ---------------- scratch ----------------
static __device__ __nv_bfloat16 g_xh[(size_t)M_ * E_];
static __device__ __nv_bfloat16 g_xl[(size_t)M_ * E_];
static __device__ __nv_bfloat16 g_qh[(size_t)M_ * E_];
static __device__ __nv_bfloat16 g_ql[(size_t)M_ * E_];
static __device__ __nv_bfloat16 g_kh[(size_t)M_ * E_];
static __device__ __nv_bfloat16 g_kl[(size_t)M_ * E_];
static __device__ __nv_bfloat16 g_vh[(size_t)M_ * E_];
static __device__ __nv_bfloat16 g_vl[(size_t)M_ * E_];
static __device__ __nv_bfloat16 g_ah[(size_t)M_ * E_];
static __device__ __nv_bfloat16 g_al[(size_t)M_ * E_];
static __device__ __nv_bfloat16 g_wqh[(size_t)E_ * E_];
static __device__ __nv_bfloat16 g_wql[(size_t)E_ * E_];
static __device__ __nv_bfloat16 g_wkh[(size_t)E_ * E_];
static __device__ __nv_bfloat16 g_wkl[(size_t)E_ * E_];
static __device__ __nv_bfloat16 g_wvh[(size_t)E_ * E_];
static __device__ __nv_bfloat16 g_wvl[(size_t)E_ * E_];
static __device__ __nv_bfloat16 g_woh[(size_t)E_ * E_];
static __device__ __nv_bfloat16 g_wol[(size_t)E_ * E_];

// ---------------- helpers ----------------
__device__ __forceinline__ uint32_t smem_u32(const void* p) {
    uint32_t a;
    asm("{ .reg .u64 t; cvta.to.shared.u64 t, %1; cvt.u32.u64 %0, t; }"
        : "=r"(a) : "l"(p));
    return a;
}
__device__ __forceinline__ void cp_async16(uint32_t saddr, const void* gaddr) {
    asm volatile("cp.async.cg.shared.global [%0], [%1], 16;\n"
                 :: "r"(saddr), "l"(gaddr));
}
#define CP_COMMIT() asm volatile("cp.async.commit_group;\n" ::: "memory")
#define CP_WAIT0()  asm volatile("cp.async.wait_group 0;\n" ::: "memory")
#define CP_WAIT1()  asm volatile("cp.async.wait_group 1;\n" ::: "memory")
#define CP_WAIT2()  asm volatile("cp.async.wait_group 2;\n" ::: "memory")

__device__ __forceinline__ void ldm_x4(uint32_t* r, uint32_t addr) {
    asm volatile("ldmatrix.sync.aligned.m8n8.x4.shared.b16 {%0,%1,%2,%3}, [%4];"
                 : "=r"(r[0]), "=r"(r[1]), "=r"(r[2]), "=r"(r[3]) : "r"(addr));
}
__device__ __forceinline__ void ldm_x4t(uint32_t* r, uint32_t addr) {
    asm volatile("ldmatrix.sync.aligned.m8n8.x4.trans.shared.b16 {%0,%1,%2,%3}, [%4];"
                 : "=r"(r[0]), "=r"(r[1]), "=r"(r[2]), "=r"(r[3]) : "r"(addr));
}
__device__ __forceinline__ void mma16816(float* d, const uint32_t* a,
                                         uint32_t b0, uint32_t b1) {
    asm volatile(
        "mma.sync.aligned.m16n8k16.row.col.f32.bf16.bf16.f32 "
        "{%0,%1,%2,%3}, {%4,%5,%6,%7}, {%8,%9}, {%0,%1,%2,%3};"
        : "+f"(d[0]), "+f"(d[1]), "+f"(d[2]), "+f"(d[3])
        : "r"(a[0]), "r"(a[1]), "r"(a[2]), "r"(a[3]), "r"(b0), "r"(b1));
}
__device__ __forceinline__ uint32_t packbf(float lo, float hi) {
    uint32_t d;
    asm("cvt.rn.bf16x2.f32 %0, %1, %2;" : "=r"(d) : "f"(hi), "f"(lo));
    return d;
}
__device__ __forceinline__ float bf_lo(uint32_t u) { return __uint_as_float(u << 16); }
__device__ __forceinline__ float bf_hi(uint32_t u) { return __uint_as_float(u & 0xffff0000u); }
__device__ __forceinline__ float ex2(float x) {
    float y; asm("ex2.approx.f32 %0, %1;" : "=f"(y) : "f"(x)); return y;
}

// ---------------------------------------------------------------------------
__global__ void split_f32(const float* __restrict__ x,
                          __nv_bfloat16* __restrict__ hi,
                          __nv_bfloat16* __restrict__ lo, int n4)
{
    int i = blockIdx.x * blockDim.x + threadIdx.x;
    if (i >= n4) return;
    float4 v = ((const float4*)x)[i];
    uint32_t h0 = packbf(v.x, v.y);
    uint32_t h1 = packbf(v.z, v.w);
    uint32_t l0 = packbf(v.x - bf_lo(h0), v.y - bf_hi(h0));
    uint32_t l1 = packbf(v.z - bf_lo(h1), v.w - bf_hi(h1));
    ((uint2*)hi)[i] = make_uint2(h0, h1);
    ((uint2*)lo)[i] = make_uint2(l0, l1);
}

// ---------------------------------------------------------------------------
// Split-bf16 HMMA GEMM: C = A @ B^T + bias.
// CTA 128m x 256n, BK=32, 8 warps (2m x 4n), warp tile 64x64, 3-stage cp.async.
// blockIdx.z selects among up to 3 (B, bias, C) argument sets.
// ---------------------------------------------------------------------------
#define GK 2048
#define NCH (GK / 32)
#define STAGE 49152
#define GSMEM (3 * STAGE)

struct GArgs {
    const __nv_bfloat16 *Bh, *Bl;
    const float* bias;
    __nv_bfloat16 *Ch, *Cl;
    float* C;
};

__device__ __forceinline__ void g3_load(
    const __nv_bfloat16* __restrict__ Ah, const __nv_bfloat16* __restrict__ Al,
    const __nv_bfloat16* __restrict__ Bh, const __nv_bfloat16* __restrict__ Bl,
    int m0, int n0, int k0, uint32_t sb, int t)
{
#pragma unroll
    for (int i = 0; i < 2; i++) {                 // A: 128 rows x 64B (h+l)
        int idx = t + i * 256, r = idx >> 2, c = idx & 3;
        uint32_t so = (uint32_t)(r * 64 + (((c ^ ((r >> 1) & 3))) << 4));
        size_t g = (size_t)(m0 + r) * GK + k0 + c * 8;
        cp_async16(sb +         so, Ah + g);
        cp_async16(sb + 8192u + so, Al + g);
    }
#pragma unroll
    for (int i = 0; i < 4; i++) {                 // B: 256 rows x 64B (h+l)
        int idx = t + i * 256, r = idx >> 2, c = idx & 3;
        uint32_t so = (uint32_t)(r * 64 + (((c ^ ((r >> 1) & 3))) << 4));
        size_t g = (size_t)(n0 + r) * GK + k0 + c * 8;
        cp_async16(sb + 16384u + so, Bh + g);
        cp_async16(sb + 32768u + so, Bl + g);
    }
}

template<bool SPLIT>
__global__ __launch_bounds__(256, 1) void gemm3(
    const __nv_bfloat16* __restrict__ Ah, const __nv_bfloat16* __restrict__ Al,
    GArgs a0, GArgs a1, GArgs a2)
{
    extern __shared__ char smem[];
    const uint32_t sbase = smem_u32(smem);
    const GArgs ga = (blockIdx.z == 0) ? a0 : (blockIdx.z == 1) ? a1 : a2;
    const int t = threadIdx.x, lane = t & 31, wid = t >> 5;
    const int warp_m = wid >> 2, warp_n = wid & 3;
    const int m0 = blockIdx.y * 128;
    const int n0 = blockIdx.x * 256;

    float acc[4][8][4];
#pragma unroll
    for (int i = 0; i < 4; i++)
#pragma unroll
        for (int j = 0; j < 8; j++)
#pragma unroll
            for (int q = 0; q < 4; q++) acc[i][j][q] = 0.f;

    g3_load(Ah, Al, ga.Bh, ga.Bl, m0, n0, 0,  sbase,             t); CP_COMMIT();
    g3_load(Ah, Al, ga.Bh, ga.Bl, m0, n0, 32, sbase + STAGE,     t); CP_COMMIT();
    g3_load(Ah, Al, ga.Bh, ga.Bl, m0, n0, 64, sbase + 2 * STAGE, t); CP_COMMIT();

    uint32_t stg = 0;
    for (int ch = 0; ch < NCH; ch++) {
        CP_WAIT2();
        __syncthreads();
        const uint32_t sb = sbase + stg * STAGE;

#pragma unroll
        for (int s = 0; s < 2; s++) {
            uint32_t Af[2][4][4];
            uint32_t Bf[2][4][4];
#pragma unroll
            for (int mt = 0; mt < 4; mt++) {
                int row = warp_m * 64 + mt * 16 + (lane & 15);
                uint32_t c = (uint32_t)(s * 2) + (uint32_t)(lane >> 4);
                uint32_t off = (uint32_t)(row * 64) + ((c ^ (uint32_t)((row >> 1) & 3)) << 4);
                ldm_x4(Af[0][mt], sb + off);
                ldm_x4(Af[1][mt], sb + 8192u + off);
            }
#pragma unroll
            for (int np = 0; np < 4; np++) {
                int row = warp_n * 64 + np * 16 + (lane & 7) + ((lane >> 4) & 1) * 8;
                uint32_t c = (uint32_t)(s * 2) + (uint32_t)((lane >> 3) & 1);
                uint32_t off = (uint32_t)(row * 64) + ((c ^ (uint32_t)((row >> 1) & 3)) << 4);
                ldm_x4(Bf[0][np], sb + 16384u + off);
                ldm_x4(Bf[1][np], sb + 32768u + off);
            }
#pragma unroll
            for (int mt = 0; mt < 4; mt++)
#pragma unroll
                for (int np = 0; np < 4; np++)
#pragma unroll
                    for (int nt2 = 0; nt2 < 2; nt2++) {
                        const int nt = np * 2 + nt2, hl = nt2 * 2;
                        mma16816(acc[mt][nt], Af[0][mt], Bf[0][np][hl], Bf[0][np][hl+1]);
                        mma16816(acc[mt][nt], Af[0][mt], Bf[1][np][hl], Bf[1][np][hl+1]);
                        mma16816(acc[mt][nt], Af[1][mt], Bf[0][np][hl], Bf[0][np][hl+1]);
                    }
        }
        __syncthreads();
        if (ch + 3 < NCH)
            g3_load(Ah, Al, ga.Bh, ga.Bl, m0, n0, (ch + 3) * 32,
                    sbase + stg * STAGE, t);
        CP_COMMIT();
        stg = (stg == 2) ? 0 : stg + 1;
    }

#pragma unroll
    for (int mt = 0; mt < 4; mt++) {
#pragma unroll
        for (int nt = 0; nt < 8; nt++) {
            const int r0 = m0 + warp_m * 64 + mt * 16 + (lane >> 2);
            const int cc = n0 + warp_n * 64 + nt * 8 + (lane & 3) * 2;
            const float bx = ga.bias[cc], by = ga.bias[cc + 1];
            float v0 = acc[mt][nt][0] + bx, v1 = acc[mt][nt][1] + by;
            float v2 = acc[mt][nt][2] + bx, v3 = acc[mt][nt][3] + by;
            if (!SPLIT) {
                *(float2*)(ga.C + (size_t)r0 * GK + cc)       = make_float2(v0, v1);
                *(float2*)(ga.C + (size_t)(r0 + 8) * GK + cc) = make_float2(v2, v3);
            } else {
                uint32_t h0 = packbf(v0, v1);
                uint32_t l0 = packbf(v0 - bf_lo(h0), v1 - bf_hi(h0));
                uint32_t h1 = packbf(v2, v3);
                uint32_t l1 = packbf(v2 - bf_lo(h1), v3 - bf_hi(h1));
                *(uint32_t*)(ga.Ch + (size_t)r0 * GK + cc)       = h0;
                *(uint32_t*)(ga.Cl + (size_t)r0 * GK + cc)       = l0;
                *(uint32_t*)(ga.Ch + (size_t)(r0 + 8) * GK + cc) = h1;
                *(uint32_t*)(ga.Cl + (size_t)(r0 + 8) * GK + cc) = l1;
            }
        }
    }
}

// ---------------------------------------------------------------------------
// Flash attention (causal), HMMA split-bf16, Q fragments register-resident.
// CTA: 256 queries x one (b,h). 2-stage KV cp.async (32KB/stage).
// ---------------------------------------------------------------------------
#define FQT 256
#define FKT 64
#define FA_SMEM 65536

__global__ __launch_bounds__(256, 1) void flash_hmma(
    const __nv_bfloat16* __restrict__ Qh, const __nv_bfloat16* __restrict__ Ql,
    const __nv_bfloat16* __restrict__ Kh, const __nv_bfloat16* __restrict__ Kl,
    const __nv_bfloat16* __restrict__ Vh, const __nv_bfloat16* __restrict__ Vl,
    __nv_bfloat16* __restrict__ Oh, __nv_bfloat16* __restrict__ Ol)
{
    extern __shared__ char smem[];
    const uint32_t sb = smem_u32(smem);
    const int t = threadIdx.x, lane = t & 31, wid = t >> 5;
    const int qt = blockIdx.x, bh = blockIdx.y;
    const int b = bh >> 5, h = bh & 31;
    const int q0 = qt * FQT;
    const size_t qbase = ((size_t)b * S_ + q0) * E_ + h * D_;
    const size_t kbase = ((size_t)b * S_) * E_ + h * D_;

    // ---- stage Q through smem (Qh -> stage0, Ql -> stage1), hoist to regs ----
#pragma unroll
    for (int i = 0; i < 8; i++) {
        int idx = t + i * 256, r = idx >> 3, c = idx & 7;
        uint32_t so = (uint32_t)(r * 128 + (((c ^ (r & 7))) << 4));
        size_t g = qbase + (size_t)r * E_ + c * 8;
        cp_async16(sb +          so, Qh + g);
        cp_async16(sb + 32768u + so, Ql + g);
    }
    CP_COMMIT();
    CP_WAIT0();
    __syncthreads();

    uint32_t fQh[2][4][4], fQl[2][4][4];
#pragma unroll
    for (int mt = 0; mt < 2; mt++)
#pragma unroll
        for (int kc = 0; kc < 4; kc++) {
            int row = wid * 32 + mt * 16 + (lane & 15);
            uint32_t c = (uint32_t)(2 * kc) + (uint32_t)(lane >> 4);
            uint32_t off = (uint32_t)(row * 128) + ((c ^ (uint32_t)(row & 7)) << 4);
            ldm_x4(fQh[mt][kc], sb + off);
            ldm_x4(fQl[mt][kc], sb + 32768u + off);
        }
    __syncthreads();

    const int jmax = 4 * (qt + 1);
    // KV tile 0 -> stage 0
#pragma unroll
    for (int i = 0; i < 2; i++) {
        int idx = t + i * 256, r = idx >> 3, c = idx & 7;
        uint32_t so = (uint32_t)(r * 128 + (((c ^ (r & 7))) << 4));
        size_t g = kbase + (size_t)r * E_ + c * 8;
        cp_async16(sb +          so, Kh + g);
        cp_async16(sb +  8192u + so, Kl + g);
        cp_async16(sb + 16384u + so, Vh + g);
        cp_async16(sb + 24576u + so, Vl + g);
    }
    CP_COMMIT();

    float Oacc[2][8][4];
#pragma unroll
    for (int i = 0; i < 2; i++)
#pragma unroll
        for (int j = 0; j < 8; j++)
#pragma unroll
            for (int q = 0; q < 4; q++) Oacc[i][j][q] = 0.f;
    float m_i[2][2] = {{-1e30f, -1e30f}, {-1e30f, -1e30f}};
    float l_i[2][2] = {{0.f, 0.f}, {0.f, 0.f}};
    const float CEXP = SCALE_ * 1.4426950408889634f;

    for (int jt = 0; jt < jmax; jt++) {
        const int k0 = jt * FKT;
        __syncthreads();
        if (jt + 1 < jmax) {
            uint32_t st = (uint32_t)((jt + 1) & 1) * 32768u;
#pragma unroll
            for (int i = 0; i < 2; i++) {
                int idx = t + i * 256, r = idx >> 3, c = idx & 7;
                uint32_t so = (uint32_t)(r * 128 + (((c ^ (r & 7))) << 4));
                size_t g = kbase + (size_t)(k0 + FKT + r) * E_ + c * 8;
                cp_async16(sb + st +          so, Kh + g);
                cp_async16(sb + st +  8192u + so, Kl + g);
                cp_async16(sb + st + 16384u + so, Vh + g);
                cp_async16(sb + st + 24576u + so, Vl + g);
            }
        }
        CP_COMMIT();
        CP_WAIT1();
        __syncthreads();
        const uint32_t sKh = sb + (uint32_t)(jt & 1) * 32768u;
        const uint32_t sKl = sKh + 8192u;
        const uint32_t sVh = sKh + 16384u;
        const uint32_t sVl = sKh + 24576u;

        // ---- S = Q K^T ----
        float sacc[2][8][4];
#pragma unroll
        for (int i = 0; i < 2; i++)
#pragma unroll
            for (int j = 0; j < 8; j++)
#pragma unroll
                for (int q = 0; q < 4; q++) sacc[i][j][q] = 0.f;

#pragma unroll
        for (int kc = 0; kc < 4; kc++) {
#pragma unroll
            for (int np = 0; np < 4; np++) {
                int row = np * 16 + (lane & 7) + ((lane >> 4) & 1) * 8;
                uint32_t c = (uint32_t)(2 * kc) + (uint32_t)((lane >> 3) & 1);
                uint32_t off = (uint32_t)(row * 128) + ((c ^ (uint32_t)(row & 7)) << 4);
                uint32_t bkh[4], bkl[4];
                ldm_x4(bkh, sKh + off);
                ldm_x4(bkl, sKl + off);
#pragma unroll
                for (int nt2 = 0; nt2 < 2; nt2++) {
                    const int snt = np * 2 + nt2;
#pragma unroll
                    for (int mt = 0; mt < 2; mt++) {
                        mma16816(sacc[mt][snt], fQh[mt][kc], bkh[nt2*2], bkh[nt2*2+1]);
                        mma16816(sacc[mt][snt], fQh[mt][kc], bkl[nt2*2], bkl[nt2*2+1]);
                        mma16816(sacc[mt][snt], fQl[mt][kc], bkh[nt2*2], bkh[nt2*2+1]);
                    }
                }
            }
        }

        // ---- causal mask ----
        if (k0 + FKT - 1 > q0) {
#pragma unroll
            for (int mt = 0; mt < 2; mt++)
#pragma unroll
                for (int nt = 0; nt < 8; nt++)
#pragma unroll
                    for (int e = 0; e < 4; e++) {
                        int qrow = q0 + wid * 32 + mt * 16 + (lane >> 2) + (e >> 1) * 8;
                        int kcol = k0 + nt * 8 + (lane & 3) * 2 + (e & 1);
                        if (kcol > qrow) sacc[mt][nt][e] = -1e30f;
                    }
        }

        // ---- online softmax ----
#pragma unroll
        for (int mt = 0; mt < 2; mt++)
#pragma unroll
            for (int rr = 0; rr < 2; rr++) {
                float mx = -1e30f;
#pragma unroll
                for (int nt = 0; nt < 8; nt++)
                    mx = fmaxf(mx, fmaxf(sacc[mt][nt][rr*2], sacc[mt][nt][rr*2+1]));
                mx = fmaxf(mx, __shfl_xor_sync(0xffffffffu, mx, 1));
                mx = fmaxf(mx, __shfl_xor_sync(0xffffffffu, mx, 2));
                const float m_new = fmaxf(m_i[mt][rr], mx);
                const float mC = m_new * CEXP;
                const float alpha = ex2(m_i[mt][rr] * CEXP - mC);
                float rs = 0.f;
#pragma unroll
                for (int nt = 0; nt < 8; nt++) {
                    float p0 = ex2(sacc[mt][nt][rr*2]   * CEXP - mC);
                    float p1 = ex2(sacc[mt][nt][rr*2+1] * CEXP - mC);
                    sacc[mt][nt][rr*2] = p0; sacc[mt][nt][rr*2+1] = p1;
                    rs += p0 + p1;
                }
                rs += __shfl_xor_sync(0xffffffffu, rs, 1);
                rs += __shfl_xor_sync(0xffffffffu, rs, 2);
                l_i[mt][rr] = l_i[mt][rr] * alpha + rs;
                m_i[mt][rr] = m_new;
#pragma unroll
                for (int nd = 0; nd < 8; nd++) {
                    Oacc[mt][nd][rr*2]   *= alpha;
                    Oacc[mt][nd][rr*2+1] *= alpha;
                }
            }

        // ---- O += P V ----
#pragma unroll
        for (int kc = 0; kc < 4; kc++) {
            uint32_t ph[2][4], pl[2][4];
#pragma unroll
            for (int mt = 0; mt < 2; mt++) {
                float p00 = sacc[mt][2*kc][0],   p01 = sacc[mt][2*kc][1];
                float p10 = sacc[mt][2*kc][2],   p11 = sacc[mt][2*kc][3];
                float p20 = sacc[mt][2*kc+1][0], p21 = sacc[mt][2*kc+1][1];
                float p30 = sacc[mt][2*kc+1][2], p31 = sacc[mt][2*kc+1][3];
                ph[mt][0] = packbf(p00, p01);
                ph[mt][1] = packbf(p10, p11);
                ph[mt][2] = packbf(p20, p21);
                ph[mt][3] = packbf(p30, p31);
                pl[mt][0] = packbf(p00 - bf_lo(ph[mt][0]), p01 - bf_hi(ph[mt][0]));
                pl[mt][1] = packbf(p10 - bf_lo(ph[mt][1]), p11 - bf_hi(ph[mt][1]));
                pl[mt][2] = packbf(p20 - bf_lo(ph[mt][2]), p21 - bf_hi(ph[mt][2]));
                pl[mt][3] = packbf(p30 - bf_lo(ph[mt][3]), p31 - bf_hi(ph[mt][3]));
            }
#pragma unroll
            for (int ndp = 0; ndp < 4; ndp++) {
                int row = kc * 16 + (lane & 7) + ((lane >> 3) & 1) * 8;
                uint32_t c = (uint32_t)(2 * ndp) + (uint32_t)(lane >> 4);
                uint32_t off = (uint32_t)(row * 128) + ((c ^ (uint32_t)(row & 7)) << 4);
                uint32_t bvh[4], bvl[4];
                ldm_x4t(bvh, sVh + off);
                ldm_x4t(bvl, sVl + off);
#pragma unroll
                for (int nt2 = 0; nt2 < 2; nt2++) {
                    const int nd = ndp * 2 + nt2;
#pragma unroll
                    for (int mt = 0; mt < 2; mt++) {
                        mma16816(Oacc[mt][nd], ph[mt], bvh[nt2*2], bvh[nt2*2+1]);
                        mma16816(Oacc[mt][nd], ph[mt], bvl[nt2*2], bvl[nt2*2+1]);
                        mma16816(Oacc[mt][nd], pl[mt], bvh[nt2*2], bvh[nt2*2+1]);
                    }
                }
            }
        }
    }

    // ---- epilogue ----
#pragma unroll
    for (int mt = 0; mt < 2; mt++)
#pragma unroll
        for (int rr = 0; rr < 2; rr++) {
            const int row = wid * 32 + mt * 16 + (lane >> 2) + rr * 8;
            const float inv = 1.f / l_i[mt][rr];
            const size_t rb = qbase + (size_t)row * E_ + (lane & 3) * 2;
#pragma unroll
            for (int nd = 0; nd < 8; nd++) {
                float v0 = Oacc[mt][nd][rr*2]   * inv;
                float v1 = Oacc[mt][nd][rr*2+1] * inv;
                uint32_t hp = packbf(v0, v1);
                uint32_t lp = packbf(v0 - bf_lo(hp), v1 - bf_hi(hp));
                *(uint32_t*)(Oh + rb + nd * 8) = hp;
                *(uint32_t*)(Ol + rb + nd * 8) = lp;
            }
        }
}

// ---------------------------------------------------------------------------
extern "C" void kernel_launch(void* const* d_in, const int* in_sizes, int n_in,
                              void* d_out, int out_size)
{
    const float* x  = (const float*)d_in[0];
    const float* Wq = (const float*)d_in[1];
    const float* bq = (const float*)d_in[2];
    const float* Wk = (const float*)d_in[3];
    const float* bk = (const float*)d_in[4];
    const float* Wv = (const float*)d_in[5];
    const float* bv = (const float*)d_in[6];
    const float* Wo = (const float*)d_in[7];
    const float* bo = (const float*)d_in[8];
    float* out = (float*)d_out;

    __nv_bfloat16 *xh, *xl, *qh, *ql, *kh, *kl, *vh, *vl, *ah, *al;
    __nv_bfloat16 *wqh, *wql, *wkh, *wkl, *wvh, *wvl, *woh, *wol;
    cudaGetSymbolAddress((void**)&xh, g_xh);
    cudaGetSymbolAddress((void**)&xl, g_xl);
    cudaGetSymbolAddress((void**)&qh, g_qh);
    cudaGetSymbolAddress((void**)&ql, g_ql);
    cudaGetSymbolAddress((void**)&kh, g_kh);
    cudaGetSymbolAddress((void**)&kl, g_kl);
    cudaGetSymbolAddress((void**)&vh, g_vh);
    cudaGetSymbolAddress((void**)&vl, g_vl);
    cudaGetSymbolAddress((void**)&ah, g_ah);
    cudaGetSymbolAddress((void**)&al, g_al);
    cudaGetSymbolAddress((void**)&wqh, g_wqh);
    cudaGetSymbolAddress((void**)&wql, g_wql);
    cudaGetSymbolAddress((void**)&wkh, g_wkh);
    cudaGetSymbolAddress((void**)&wkl, g_wkl);
    cudaGetSymbolAddress((void**)&wvh, g_wvh);
    cudaGetSymbolAddress((void**)&wvl, g_wvl);
    cudaGetSymbolAddress((void**)&woh, g_woh);
    cudaGetSymbolAddress((void**)&wol, g_wol);

    cudaFuncSetAttribute(gemm3<true>,
                         cudaFuncAttributeMaxDynamicSharedMemorySize, GSMEM);
    cudaFuncSetAttribute(gemm3<false>,
                         cudaFuncAttributeMaxDynamicSharedMemorySize, GSMEM);
    cudaFuncSetAttribute(flash_hmma,
                         cudaFuncAttributeMaxDynamicSharedMemorySize, FA_SMEM);

    const int n4x = (M_ * E_) / 4;
    const int n4w = (E_ * E_) / 4;
    split_f32<<<(n4x + 255) / 256, 256>>>(x,  xh,  xl,  n4x);
    split_f32<<<(n4w + 255) / 256, 256>>>(Wq, wqh, wql, n4w);
    split_f32<<<(n4w + 255) / 256, 256>>>(Wk, wkh, wkl, n4w);
    split_f32<<<(n4w + 255) / 256, 256>>>(Wv, wvh, wvl, n4w);
    split_f32<<<(n4w + 255) / 256, 256>>>(Wo, woh, wol, n4w);

    GArgs aq{wqh, wql, bq, qh, ql, nullptr};
    GArgs ak{wkh, wkl, bk, kh, kl, nullptr};
    GArgs av{wvh, wvl, bv, vh, vl, nullptr};
    GArgs ao{woh, wol, bo, nullptr, nullptr, out};

    dim3 gq(E_ / 256, M_ / 128, 3);   // (8, 32, 3)
    gemm3<true><<<gq, 256, GSMEM>>>(xh, xl, aq, ak, av);

    dim3 ga(S_ / FQT, B_ * H_);       // (8, 64)
    flash_hmma<<<ga, 256, FA_SMEM>>>(qh, ql, kh, kl, vh, vl, ah, al);

    dim3 go(E_ / 256, M_ / 128, 1);   // (8, 32, 1)
    gemm3<false><<<go, 256, GSMEM>>>(ah, al, ao, ao, ao);
}

// round 6
// speedup vs baseline: 1.5354x; 1.5354x over previous
#include <cuda_runtime.h>
#include <cuda_bf16.h>
#include <cstdint>
#include <math.h>

#define B_ 2
#define S_ 2048
#define E_ 2048
#define H_ 32
#define D_ 64
#define M_ (B_*S_)
#define SCALE_ 0.125f

// ---------------- scratch ----------------
static __device__ int8_t g_x1[(size_t)M_ * E_];
static __device__ int8_t g_x2[(size_t)M_ * E_];
static __device__ float  g_sx[M_];
static __device__ int8_t g_a1[(size_t)M_ * E_];
static __device__ int8_t g_a2[(size_t)M_ * E_];
static __device__ float  g_sa[M_];
static __device__ float  g_attn[(size_t)M_ * E_];

static __device__ int8_t g_wq1[(size_t)E_ * E_];
static __device__ int8_t g_wq2[(size_t)E_ * E_];
static __device__ float  g_swq[E_];
static __device__ int8_t g_wk1[(size_t)E_ * E_];
static __device__ int8_t g_wk2[(size_t)E_ * E_];
static __device__ float  g_swk[E_];
static __device__ int8_t g_wv1[(size_t)E_ * E_];
static __device__ int8_t g_wv2[(size_t)E_ * E_];
static __device__ float  g_swv[E_];
static __device__ int8_t g_wo1[(size_t)E_ * E_];
static __device__ int8_t g_wo2[(size_t)E_ * E_];
static __device__ float  g_swo[E_];

static __device__ __nv_bfloat16 g_qh[(size_t)M_ * E_];
static __device__ __nv_bfloat16 g_ql[(size_t)M_ * E_];
static __device__ __nv_bfloat16 g_kh[(size_t)M_ * E_];
static __device__ __nv_bfloat16 g_kl[(size_t)M_ * E_];
static __device__ __nv_bfloat16 g_vh[(size_t)M_ * E_];
static __device__ __nv_bfloat16 g_vl[(size_t)M_ * E_];

// ---------------- helpers ----------------
__device__ __forceinline__ uint32_t smem_u32(const void* p) {
    uint32_t a;
    asm("{ .reg .u64 t; cvta.to.shared.u64 t, %1; cvt.u32.u64 %0, t; }"
        : "=r"(a) : "l"(p));
    return a;
}
__device__ __forceinline__ void cp_async16(uint32_t saddr, const void* gaddr) {
    asm volatile("cp.async.cg.shared.global [%0], [%1], 16;\n"
                 :: "r"(saddr), "l"(gaddr));
}
#define CP_COMMIT() asm volatile("cp.async.commit_group;\n" ::: "memory")
#define CP_WAIT0()  asm volatile("cp.async.wait_group 0;\n" ::: "memory")
#define CP_WAIT1()  asm volatile("cp.async.wait_group 1;\n" ::: "memory")
#define CP_WAIT2()  asm volatile("cp.async.wait_group 2;\n" ::: "memory")

__device__ __forceinline__ void ldm_x4(uint32_t* r, uint32_t addr) {
    asm volatile("ldmatrix.sync.aligned.m8n8.x4.shared.b16 {%0,%1,%2,%3}, [%4];"
                 : "=r"(r[0]), "=r"(r[1]), "=r"(r[2]), "=r"(r[3]) : "r"(addr));
}
__device__ __forceinline__ void ldm_x4t(uint32_t* r, uint32_t addr) {
    asm volatile("ldmatrix.sync.aligned.m8n8.x4.trans.shared.b16 {%0,%1,%2,%3}, [%4];"
                 : "=r"(r[0]), "=r"(r[1]), "=r"(r[2]), "=r"(r[3]) : "r"(addr));
}
__device__ __forceinline__ void mma16816(float* d, const uint32_t* a,
                                         uint32_t b0, uint32_t b1) {
    asm volatile(
        "mma.sync.aligned.m16n8k16.row.col.f32.bf16.bf16.f32 "
        "{%0,%1,%2,%3}, {%4,%5,%6,%7}, {%8,%9}, {%0,%1,%2,%3};"
        : "+f"(d[0]), "+f"(d[1]), "+f"(d[2]), "+f"(d[3])
        : "r"(a[0]), "r"(a[1]), "r"(a[2]), "r"(a[3]), "r"(b0), "r"(b1));
}
__device__ __forceinline__ void mma_s8(int* d, const uint32_t* a,
                                       uint32_t b0, uint32_t b1) {
    asm volatile(
        "mma.sync.aligned.m16n8k32.row.col.s32.s8.s8.s32 "
        "{%0,%1,%2,%3}, {%4,%5,%6,%7}, {%8,%9}, {%0,%1,%2,%3};"
        : "+r"(d[0]), "+r"(d[1]), "+r"(d[2]), "+r"(d[3])
        : "r"(a[0]), "r"(a[1]), "r"(a[2]), "r"(a[3]), "r"(b0), "r"(b1));
}
__device__ __forceinline__ uint32_t packbf(float lo, float hi) {
    uint32_t d;
    asm("cvt.rn.bf16x2.f32 %0, %1, %2;" : "=r"(d) : "f"(hi), "f"(lo));
    return d;
}
__device__ __forceinline__ float bf_lo(uint32_t u) { return __uint_as_float(u << 16); }
__device__ __forceinline__ float bf_hi(uint32_t u) { return __uint_as_float(u & 0xffff0000u); }
__device__ __forceinline__ float ex2(float x) {
    float y; asm("ex2.approx.f32 %0, %1;" : "=f"(y) : "f"(x)); return y;
}

// ---------------------------------------------------------------------------
// Row-wise two-level int8 quantization. cols fixed = 2048, 256 thr (8 elem ea).
// x ~= s * (q1 + q2/254), |err| <= s * 2^-9.
// ---------------------------------------------------------------------------
__global__ __launch_bounds__(256) void rowquant(
    const float* __restrict__ x, int8_t* __restrict__ q1,
    int8_t* __restrict__ q2, float* __restrict__ s)
{
    __shared__ float wmax[8];
    const int row = blockIdx.x, t = threadIdx.x;
    const float* xr = x + (size_t)row * 2048 + t * 8;
    float4 v0 = ((const float4*)xr)[0];
    float4 v1 = ((const float4*)xr)[1];
    float vv[8] = {v0.x, v0.y, v0.z, v0.w, v1.x, v1.y, v1.z, v1.w};
    float m = 0.f;
#pragma unroll
    for (int j = 0; j < 8; j++) m = fmaxf(m, fabsf(vv[j]));
#pragma unroll
    for (int o = 16; o; o >>= 1) m = fmaxf(m, __shfl_xor_sync(~0u, m, o));
    if ((t & 31) == 0) wmax[t >> 5] = m;
    __syncthreads();
    float mm = wmax[0];
#pragma unroll
    for (int i = 1; i < 8; i++) mm = fmaxf(mm, wmax[i]);
    mm = fmaxf(mm, 1e-20f);
    if (t == 0) s[row] = mm * (1.f / 127.f);
    const float inv = 127.f / mm;

    uint32_t p1[2] = {0, 0}, p2[2] = {0, 0};
#pragma unroll
    for (int j = 0; j < 8; j++) {
        float xs = vv[j] * inv;
        float qf = rintf(xs);
        float rf = rintf((xs - qf) * 254.f);
        int iq = (int)qf, ir = (int)rf;
        p1[j >> 2] |= (uint32_t)(iq & 0xff) << ((j & 3) * 8);
        p2[j >> 2] |= (uint32_t)(ir & 0xff) << ((j & 3) * 8);
    }
    ((uint32_t*)q1)[row * 512 + t * 2]     = p1[0];
    ((uint32_t*)q1)[row * 512 + t * 2 + 1] = p1[1];
    ((uint32_t*)q2)[row * 512 + t * 2]     = p2[0];
    ((uint32_t*)q2)[row * 512 + t * 2 + 1] = p2[1];
}

// ---------------------------------------------------------------------------
// Two-level int8 GEMM: C = sA_i*sB_j*(A1B1 + (A1B2+A2B1)/254) + bias.
// CTA 128x128, BK=64 int8, 8 warps (2m x 4n), warp tile 64x32, 3-stage.
// blockIdx.z selects among 3 (B, C) argument sets.
// ---------------------------------------------------------------------------
#define GK 2048
#define NCH8 32
#define SSTG 32768
#define GS8_SMEM (3 * SSTG)

struct GArgs {
    const int8_t *B1, *B2;
    const float* sB;
    const float* bias;
    __nv_bfloat16 *Ch, *Cl;
    float* C;
};

__device__ __forceinline__ void s8_load(
    const int8_t* __restrict__ A1, const int8_t* __restrict__ A2,
    const int8_t* __restrict__ B1, const int8_t* __restrict__ B2,
    int m0, int n0, int k0, uint32_t sb, int t)
{
#pragma unroll
    for (int i = 0; i < 2; i++) {
        int idx = t + i * 256, r = idx >> 2, c = idx & 3;
        uint32_t so = (uint32_t)(r * 64 + (((c ^ ((r >> 1) & 3))) << 4));
        size_t ga = (size_t)(m0 + r) * GK + k0 + c * 16;
        size_t gb = (size_t)(n0 + r) * GK + k0 + c * 16;
        cp_async16(sb +          so, A1 + ga);
        cp_async16(sb +  8192u + so, A2 + ga);
        cp_async16(sb + 16384u + so, B1 + gb);
        cp_async16(sb + 24576u + so, B2 + gb);
    }
}

template<bool SPLIT>
__global__ __launch_bounds__(256, 1) void gemm_s8(
    const int8_t* __restrict__ A1, const int8_t* __restrict__ A2,
    const float* __restrict__ sA, GArgs a0, GArgs a1, GArgs a2)
{
    extern __shared__ char smem[];
    const uint32_t sbase = smem_u32(smem);
    const GArgs ga = (blockIdx.z == 0) ? a0 : (blockIdx.z == 1) ? a1 : a2;
    const int t = threadIdx.x, lane = t & 31, wid = t >> 5;
    const int warp_m = wid >> 2, warp_n = wid & 3;
    const int m0 = blockIdx.y * 128;
    const int n0 = blockIdx.x * 128;

    int a_row[4], b_row[2];
    uint32_t a_sw[4], b_sw[2];
#pragma unroll
    for (int mt = 0; mt < 4; mt++) {
        a_row[mt] = warp_m * 64 + mt * 16 + (lane & 15);
        a_sw[mt]  = (uint32_t)((a_row[mt] >> 1) & 3);
    }
#pragma unroll
    for (int pt = 0; pt < 2; pt++) {
        b_row[pt] = warp_n * 32 + pt * 16 + (lane & 7) + ((lane >> 4) & 1) * 8;
        b_sw[pt]  = (uint32_t)((b_row[pt] >> 1) & 3);
    }
    const uint32_t a_ch = (uint32_t)(lane >> 4);
    const uint32_t b_ch = (uint32_t)((lane >> 3) & 1);

    int acc1[4][4][4], acc2[4][4][4];
#pragma unroll
    for (int i = 0; i < 4; i++)
#pragma unroll
        for (int j = 0; j < 4; j++)
#pragma unroll
            for (int q = 0; q < 4; q++) { acc1[i][j][q] = 0; acc2[i][j][q] = 0; }

    s8_load(A1, A2, ga.B1, ga.B2, m0, n0, 0,   sbase,            t); CP_COMMIT();
    s8_load(A1, A2, ga.B1, ga.B2, m0, n0, 64,  sbase + SSTG,     t); CP_COMMIT();
    s8_load(A1, A2, ga.B1, ga.B2, m0, n0, 128, sbase + 2 * SSTG, t); CP_COMMIT();

    uint32_t stg = 0;
    for (int ch = 0; ch < NCH8; ch++) {
        CP_WAIT2();
        __syncthreads();
        const uint32_t sb = sbase + stg * SSTG;

#pragma unroll
        for (int s = 0; s < 2; s++) {        // two k32 steps per 64B chunk
            uint32_t Af1[4][4], Af2[4][4];
            uint32_t Bf1[2][4], Bf2[2][4];
#pragma unroll
            for (int mt = 0; mt < 4; mt++) {
                uint32_t c = (uint32_t)(s * 2) + a_ch;
                uint32_t off = (uint32_t)(a_row[mt] * 64) + ((c ^ a_sw[mt]) << 4);
                ldm_x4(Af1[mt], sb + off);
                ldm_x4(Af2[mt], sb + 8192u + off);
            }
#pragma unroll
            for (int pt = 0; pt < 2; pt++) {
                uint32_t c = (uint32_t)(s * 2) + b_ch;
                uint32_t off = (uint32_t)(b_row[pt] * 64) + ((c ^ b_sw[pt]) << 4);
                ldm_x4(Bf1[pt], sb + 16384u + off);
                ldm_x4(Bf2[pt], sb + 24576u + off);
            }
#pragma unroll
            for (int mt = 0; mt < 4; mt++)
#pragma unroll
                for (int nt = 0; nt < 4; nt++) {
                    const int pt = nt >> 1, hl = (nt & 1) * 2;
                    mma_s8(acc1[mt][nt], Af1[mt], Bf1[pt][hl], Bf1[pt][hl+1]);
                    mma_s8(acc2[mt][nt], Af1[mt], Bf2[pt][hl], Bf2[pt][hl+1]);
                    mma_s8(acc2[mt][nt], Af2[mt], Bf1[pt][hl], Bf1[pt][hl+1]);
                }
        }
        __syncthreads();
        if (ch + 3 < NCH8)
            s8_load(A1, A2, ga.B1, ga.B2, m0, n0, (ch + 3) * 64,
                    sbase + stg * SSTG, t);
        CP_COMMIT();
        stg = (stg == 2) ? 0 : stg + 1;
    }

    const float R = 1.f / 254.f;
#pragma unroll
    for (int mt = 0; mt < 4; mt++) {
        const int r0 = m0 + warp_m * 64 + mt * 16 + (lane >> 2);
        const float sa0 = sA[r0], sa1 = sA[r0 + 8];
#pragma unroll
        for (int nt = 0; nt < 4; nt++) {
            const int cc = n0 + warp_n * 32 + nt * 8 + (lane & 3) * 2;
            const float sb0 = ga.sB[cc], sb1 = ga.sB[cc + 1];
            const float bx = ga.bias[cc], by = ga.bias[cc + 1];
            float v0 = ((float)acc1[mt][nt][0] + (float)acc2[mt][nt][0] * R) * (sa0 * sb0) + bx;
            float v1 = ((float)acc1[mt][nt][1] + (float)acc2[mt][nt][1] * R) * (sa0 * sb1) + by;
            float v2 = ((float)acc1[mt][nt][2] + (float)acc2[mt][nt][2] * R) * (sa1 * sb0) + bx;
            float v3 = ((float)acc1[mt][nt][3] + (float)acc2[mt][nt][3] * R) * (sa1 * sb1) + by;
            if (!SPLIT) {
                *(float2*)(ga.C + (size_t)r0 * GK + cc)       = make_float2(v0, v1);
                *(float2*)(ga.C + (size_t)(r0 + 8) * GK + cc) = make_float2(v2, v3);
            } else {
                uint32_t h0 = packbf(v0, v1);
                uint32_t l0 = packbf(v0 - bf_lo(h0), v1 - bf_hi(h0));
                uint32_t h1 = packbf(v2, v3);
                uint32_t l1 = packbf(v2 - bf_lo(h1), v3 - bf_hi(h1));
                *(uint32_t*)(ga.Ch + (size_t)r0 * GK + cc)       = h0;
                *(uint32_t*)(ga.Cl + (size_t)r0 * GK + cc)       = l0;
                *(uint32_t*)(ga.Ch + (size_t)(r0 + 8) * GK + cc) = h1;
                *(uint32_t*)(ga.Cl + (size_t)(r0 + 8) * GK + cc) = l1;
            }
        }
    }
}

// ---------------------------------------------------------------------------
// Flash attention (causal), HMMA split-bf16, Q register-resident.
// Writes fp32 attention output (quantized afterwards for the output GEMM).
// ---------------------------------------------------------------------------
#define FQT 256
#define FKT 64
#define FA_SMEM 65536

__global__ __launch_bounds__(256, 1) void flash_hmma(
    const __nv_bfloat16* __restrict__ Qh, const __nv_bfloat16* __restrict__ Ql,
    const __nv_bfloat16* __restrict__ Kh, const __nv_bfloat16* __restrict__ Kl,
    const __nv_bfloat16* __restrict__ Vh, const __nv_bfloat16* __restrict__ Vl,
    float* __restrict__ O)
{
    extern __shared__ char smem[];
    const uint32_t sb = smem_u32(smem);
    const int t = threadIdx.x, lane = t & 31, wid = t >> 5;
    const int qt = blockIdx.x, bh = blockIdx.y;
    const int b = bh >> 5, h = bh & 31;
    const int q0 = qt * FQT;
    const size_t qbase = ((size_t)b * S_ + q0) * E_ + h * D_;
    const size_t kbase = ((size_t)b * S_) * E_ + h * D_;

#pragma unroll
    for (int i = 0; i < 8; i++) {
        int idx = t + i * 256, r = idx >> 3, c = idx & 7;
        uint32_t so = (uint32_t)(r * 128 + (((c ^ (r & 7))) << 4));
        size_t g = qbase + (size_t)r * E_ + c * 8;
        cp_async16(sb +          so, Qh + g);
        cp_async16(sb + 32768u + so, Ql + g);
    }
    CP_COMMIT();
    CP_WAIT0();
    __syncthreads();

    uint32_t fQh[2][4][4], fQl[2][4][4];
#pragma unroll
    for (int mt = 0; mt < 2; mt++)
#pragma unroll
        for (int kc = 0; kc < 4; kc++) {
            int row = wid * 32 + mt * 16 + (lane & 15);
            uint32_t c = (uint32_t)(2 * kc) + (uint32_t)(lane >> 4);
            uint32_t off = (uint32_t)(row * 128) + ((c ^ (uint32_t)(row & 7)) << 4);
            ldm_x4(fQh[mt][kc], sb + off);
            ldm_x4(fQl[mt][kc], sb + 32768u + off);
        }
    __syncthreads();

    const int jmax = 4 * (qt + 1);
#pragma unroll
    for (int i = 0; i < 2; i++) {
        int idx = t + i * 256, r = idx >> 3, c = idx & 7;
        uint32_t so = (uint32_t)(r * 128 + (((c ^ (r & 7))) << 4));
        size_t g = kbase + (size_t)r * E_ + c * 8;
        cp_async16(sb +          so, Kh + g);
        cp_async16(sb +  8192u + so, Kl + g);
        cp_async16(sb + 16384u + so, Vh + g);
        cp_async16(sb + 24576u + so, Vl + g);
    }
    CP_COMMIT();

    float Oacc[2][8][4];
#pragma unroll
    for (int i = 0; i < 2; i++)
#pragma unroll
        for (int j = 0; j < 8; j++)
#pragma unroll
            for (int q = 0; q < 4; q++) Oacc[i][j][q] = 0.f;
    float m_i[2][2] = {{-1e30f, -1e30f}, {-1e30f, -1e30f}};
    float l_i[2][2] = {{0.f, 0.f}, {0.f, 0.f}};
    const float CEXP = SCALE_ * 1.4426950408889634f;

    for (int jt = 0; jt < jmax; jt++) {
        const int k0 = jt * FKT;
        __syncthreads();
        if (jt + 1 < jmax) {
            uint32_t st = (uint32_t)((jt + 1) & 1) * 32768u;
#pragma unroll
            for (int i = 0; i < 2; i++) {
                int idx = t + i * 256, r = idx >> 3, c = idx & 7;
                uint32_t so = (uint32_t)(r * 128 + (((c ^ (r & 7))) << 4));
                size_t g = kbase + (size_t)(k0 + FKT + r) * E_ + c * 8;
                cp_async16(sb + st +          so, Kh + g);
                cp_async16(sb + st +  8192u + so, Kl + g);
                cp_async16(sb + st + 16384u + so, Vh + g);
                cp_async16(sb + st + 24576u + so, Vl + g);
            }
        }
        CP_COMMIT();
        CP_WAIT1();
        __syncthreads();
        const uint32_t sKh = sb + (uint32_t)(jt & 1) * 32768u;
        const uint32_t sKl = sKh + 8192u;
        const uint32_t sVh = sKh + 16384u;
        const uint32_t sVl = sKh + 24576u;

        float sacc[2][8][4];
#pragma unroll
        for (int i = 0; i < 2; i++)
#pragma unroll
            for (int j = 0; j < 8; j++)
#pragma unroll
                for (int q = 0; q < 4; q++) sacc[i][j][q] = 0.f;

#pragma unroll
        for (int kc = 0; kc < 4; kc++) {
#pragma unroll
            for (int np = 0; np < 4; np++) {
                int row = np * 16 + (lane & 7) + ((lane >> 4) & 1) * 8;
                uint32_t c = (uint32_t)(2 * kc) + (uint32_t)((lane >> 3) & 1);
                uint32_t off = (uint32_t)(row * 128) + ((c ^ (uint32_t)(row & 7)) << 4);
                uint32_t bkh[4], bkl[4];
                ldm_x4(bkh, sKh + off);
                ldm_x4(bkl, sKl + off);
#pragma unroll
                for (int nt2 = 0; nt2 < 2; nt2++) {
                    const int snt = np * 2 + nt2;
#pragma unroll
                    for (int mt = 0; mt < 2; mt++) {
                        mma16816(sacc[mt][snt], fQh[mt][kc], bkh[nt2*2], bkh[nt2*2+1]);
                        mma16816(sacc[mt][snt], fQh[mt][kc], bkl[nt2*2], bkl[nt2*2+1]);
                        mma16816(sacc[mt][snt], fQl[mt][kc], bkh[nt2*2], bkh[nt2*2+1]);
                    }
                }
            }
        }

        if (k0 + FKT - 1 > q0) {
#pragma unroll
            for (int mt = 0; mt < 2; mt++)
#pragma unroll
                for (int nt = 0; nt < 8; nt++)
#pragma unroll
                    for (int e = 0; e < 4; e++) {
                        int qrow = q0 + wid * 32 + mt * 16 + (lane >> 2) + (e >> 1) * 8;
                        int kcol = k0 + nt * 8 + (lane & 3) * 2 + (e & 1);
                        if (kcol > qrow) sacc[mt][nt][e] = -1e30f;
                    }
        }

#pragma unroll
        for (int mt = 0; mt < 2; mt++)
#pragma unroll
            for (int rr = 0; rr < 2; rr++) {
                float mx = -1e30f;
#pragma unroll
                for (int nt = 0; nt < 8; nt++)
                    mx = fmaxf(mx, fmaxf(sacc[mt][nt][rr*2], sacc[mt][nt][rr*2+1]));
                mx = fmaxf(mx, __shfl_xor_sync(0xffffffffu, mx, 1));
                mx = fmaxf(mx, __shfl_xor_sync(0xffffffffu, mx, 2));
                const float m_new = fmaxf(m_i[mt][rr], mx);
                const float mC = m_new * CEXP;
                const float alpha = ex2(m_i[mt][rr] * CEXP - mC);
                float rs = 0.f;
#pragma unroll
                for (int nt = 0; nt < 8; nt++) {
                    float p0 = ex2(sacc[mt][nt][rr*2]   * CEXP - mC);
                    float p1 = ex2(sacc[mt][nt][rr*2+1] * CEXP - mC);
                    sacc[mt][nt][rr*2] = p0; sacc[mt][nt][rr*2+1] = p1;
                    rs += p0 + p1;
                }
                rs += __shfl_xor_sync(0xffffffffu, rs, 1);
                rs += __shfl_xor_sync(0xffffffffu, rs, 2);
                l_i[mt][rr] = l_i[mt][rr] * alpha + rs;
                m_i[mt][rr] = m_new;
#pragma unroll
                for (int nd = 0; nd < 8; nd++) {
                    Oacc[mt][nd][rr*2]   *= alpha;
                    Oacc[mt][nd][rr*2+1] *= alpha;
                }
            }

#pragma unroll
        for (int kc = 0; kc < 4; kc++) {
            uint32_t ph[2][4], pl[2][4];
#pragma unroll
            for (int mt = 0; mt < 2; mt++) {
                float p00 = sacc[mt][2*kc][0],   p01 = sacc[mt][2*kc][1];
                float p10 = sacc[mt][2*kc][2],   p11 = sacc[mt][2*kc][3];
                float p20 = sacc[mt][2*kc+1][0], p21 = sacc[mt][2*kc+1][1];
                float p30 = sacc[mt][2*kc+1][2], p31 = sacc[mt][2*kc+1][3];
                ph[mt][0] = packbf(p00, p01);
                ph[mt][1] = packbf(p10, p11);
                ph[mt][2] = packbf(p20, p21);
                ph[mt][3] = packbf(p30, p31);
                pl[mt][0] = packbf(p00 - bf_lo(ph[mt][0]), p01 - bf_hi(ph[mt][0]));
                pl[mt][1] = packbf(p10 - bf_lo(ph[mt][1]), p11 - bf_hi(ph[mt][1]));
                pl[mt][2] = packbf(p20 - bf_lo(ph[mt][2]), p21 - bf_hi(ph[mt][2]));
                pl[mt][3] = packbf(p30 - bf_lo(ph[mt][3]), p31 - bf_hi(ph[mt][3]));
            }
#pragma unroll
            for (int ndp = 0; ndp < 4; ndp++) {
                int row = kc * 16 + (lane & 7) + ((lane >> 3) & 1) * 8;
                uint32_t c = (uint32_t)(2 * ndp) + (uint32_t)(lane >> 4);
                uint32_t off = (uint32_t)(row * 128) + ((c ^ (uint32_t)(row & 7)) << 4);
                uint32_t bvh[4], bvl[4];
                ldm_x4t(bvh, sVh + off);
                ldm_x4t(bvl, sVl + off);
#pragma unroll
                for (int nt2 = 0; nt2 < 2; nt2++) {
                    const int nd = ndp * 2 + nt2;
#pragma unroll
                    for (int mt = 0; mt < 2; mt++) {
                        mma16816(Oacc[mt][nd], ph[mt], bvh[nt2*2], bvh[nt2*2+1]);
                        mma16816(Oacc[mt][nd], ph[mt], bvl[nt2*2], bvl[nt2*2+1]);
                        mma16816(Oacc[mt][nd], pl[mt], bvh[nt2*2], bvh[nt2*2+1]);
                    }
                }
            }
        }
    }

#pragma unroll
    for (int mt = 0; mt < 2; mt++)
#pragma unroll
        for (int rr = 0; rr < 2; rr++) {
            const int row = wid * 32 + mt * 16 + (lane >> 2) + rr * 8;
            const float inv = 1.f / l_i[mt][rr];
            const size_t rb = qbase + (size_t)row * E_ + (lane & 3) * 2;
#pragma unroll
            for (int nd = 0; nd < 8; nd++) {
                float v0 = Oacc[mt][nd][rr*2]   * inv;
                float v1 = Oacc[mt][nd][rr*2+1] * inv;
                *(float2*)(O + rb + nd * 8) = make_float2(v0, v1);
            }
        }
}

// ---------------------------------------------------------------------------
extern "C" void kernel_launch(void* const* d_in, const int* in_sizes, int n_in,
                              void* d_out, int out_size)
{
    const float* x  = (const float*)d_in[0];
    const float* Wq = (const float*)d_in[1];
    const float* bq = (const float*)d_in[2];
    const float* Wk = (const float*)d_in[3];
    const float* bk = (const float*)d_in[4];
    const float* Wv = (const float*)d_in[5];
    const float* bv = (const float*)d_in[6];
    const float* Wo = (const float*)d_in[7];
    const float* bo = (const float*)d_in[8];
    float* out = (float*)d_out;

    int8_t *x1, *x2, *a1, *a2;
    int8_t *wq1, *wq2, *wk1, *wk2, *wv1, *wv2, *wo1, *wo2;
    float *sx, *sa, *swq, *swk, *swv, *swo, *attn;
    __nv_bfloat16 *qh, *ql, *kh, *kl, *vh, *vl;
    cudaGetSymbolAddress((void**)&x1, g_x1);
    cudaGetSymbolAddress((void**)&x2, g_x2);
    cudaGetSymbolAddress((void**)&sx, g_sx);
    cudaGetSymbolAddress((void**)&a1, g_a1);
    cudaGetSymbolAddress((void**)&a2, g_a2);
    cudaGetSymbolAddress((void**)&sa, g_sa);
    cudaGetSymbolAddress((void**)&attn, g_attn);
    cudaGetSymbolAddress((void**)&wq1, g_wq1);
    cudaGetSymbolAddress((void**)&wq2, g_wq2);
    cudaGetSymbolAddress((void**)&swq, g_swq);
    cudaGetSymbolAddress((void**)&wk1, g_wk1);
    cudaGetSymbolAddress((void**)&wk2, g_wk2);
    cudaGetSymbolAddress((void**)&swk, g_swk);
    cudaGetSymbolAddress((void**)&wv1, g_wv1);
    cudaGetSymbolAddress((void**)&wv2, g_wv2);
    cudaGetSymbolAddress((void**)&swv, g_swv);
    cudaGetSymbolAddress((void**)&wo1, g_wo1);
    cudaGetSymbolAddress((void**)&wo2, g_wo2);
    cudaGetSymbolAddress((void**)&swo, g_swo);
    cudaGetSymbolAddress((void**)&qh, g_qh);
    cudaGetSymbolAddress((void**)&ql, g_ql);
    cudaGetSymbolAddress((void**)&kh, g_kh);
    cudaGetSymbolAddress((void**)&kl, g_kl);
    cudaGetSymbolAddress((void**)&vh, g_vh);
    cudaGetSymbolAddress((void**)&vl, g_vl);

    cudaFuncSetAttribute(gemm_s8<true>,
                         cudaFuncAttributeMaxDynamicSharedMemorySize, GS8_SMEM);
    cudaFuncSetAttribute(gemm_s8<false>,
                         cudaFuncAttributeMaxDynamicSharedMemorySize, GS8_SMEM);
    cudaFuncSetAttribute(flash_hmma,
                         cudaFuncAttributeMaxDynamicSharedMemorySize, FA_SMEM);

    rowquant<<<M_, 256>>>(x,  x1,  x2,  sx);
    rowquant<<<E_, 256>>>(Wq, wq1, wq2, swq);
    rowquant<<<E_, 256>>>(Wk, wk1, wk2, swk);
    rowquant<<<E_, 256>>>(Wv, wv1, wv2, swv);
    rowquant<<<E_, 256>>>(Wo, wo1, wo2, swo);

    GArgs aq{wq1, wq2, swq, bq, qh, ql, nullptr};
    GArgs ak{wk1, wk2, swk, bk, kh, kl, nullptr};
    GArgs av{wv1, wv2, swv, bv, vh, vl, nullptr};
    GArgs ao{wo1, wo2, swo, bo, nullptr, nullptr, out};

    dim3 gq(E_ / 128, M_ / 128, 3);   // (16, 32, 3)
    gemm_s8<true><<<gq, 256, GS8_SMEM>>>(x1, x2, sx, aq, ak, av);

    dim3 ga(S_ / FQT, B_ * H_);       // (8, 64)
    flash_hmma<<<ga, 256, FA_SMEM>>>(qh, ql, kh, kl, vh, vl, attn);

    rowquant<<<M_, 256>>>(attn, a1, a2, sa);

    dim3 go(E_ / 128, M_ / 128, 1);
    gemm_s8<false><<<go, 256, GS8_SMEM>>>(a1, a2, sa, ao, ao, ao);
}

// round 7
// speedup vs baseline: 1.5361x; 1.0005x over previous
#include <cuda_runtime.h>
#include <cuda_bf16.h>
#include <cstdint>
#include <math.h>

#define B_ 2
#define S_ 2048
#define E_ 2048
#define H_ 32
#define D_ 64
#define M_ (B_*S_)
#define SCALE_ 0.125f

// ---------------- scratch ----------------
static __device__ int8_t g_x1[(size_t)M_ * E_];
static __device__ int8_t g_x2[(size_t)M_ * E_];
static __device__ float  g_sx[M_];
static __device__ int8_t g_a1[(size_t)M_ * E_];
static __device__ int8_t g_a2[(size_t)M_ * E_];
static __device__ float  g_sa[M_];
static __device__ float  g_attn[(size_t)M_ * E_];

static __device__ int8_t g_wq1[(size_t)E_ * E_];
static __device__ int8_t g_wq2[(size_t)E_ * E_];
static __device__ float  g_swq[E_];
static __device__ int8_t g_wk1[(size_t)E_ * E_];
static __device__ int8_t g_wk2[(size_t)E_ * E_];
static __device__ float  g_swk[E_];
static __device__ int8_t g_wv1[(size_t)E_ * E_];
static __device__ int8_t g_wv2[(size_t)E_ * E_];
static __device__ float  g_swv[E_];
static __device__ int8_t g_wo1[(size_t)E_ * E_];
static __device__ int8_t g_wo2[(size_t)E_ * E_];
static __device__ float  g_swo[E_];

static __device__ __nv_bfloat16 g_qh[(size_t)M_ * E_];
static __device__ __nv_bfloat16 g_ql[(size_t)M_ * E_];
static __device__ __nv_bfloat16 g_kh[(size_t)M_ * E_];
static __device__ __nv_bfloat16 g_kl[(size_t)M_ * E_];
static __device__ __nv_bfloat16 g_vh[(size_t)M_ * E_];
static __device__ __nv_bfloat16 g_vl[(size_t)M_ * E_];

// ---------------- helpers ----------------
__device__ __forceinline__ uint32_t smem_u32(const void* p) {
    uint32_t a;
    asm("{ .reg .u64 t; cvta.to.shared.u64 t, %1; cvt.u32.u64 %0, t; }"
        : "=r"(a) : "l"(p));
    return a;
}
__device__ __forceinline__ void cp_async16(uint32_t saddr, const void* gaddr) {
    asm volatile("cp.async.cg.shared.global [%0], [%1], 16;\n"
                 :: "r"(saddr), "l"(gaddr));
}
#define CP_COMMIT() asm volatile("cp.async.commit_group;\n" ::: "memory")
#define CP_WAIT0()  asm volatile("cp.async.wait_group 0;\n" ::: "memory")
#define CP_WAIT1()  asm volatile("cp.async.wait_group 1;\n" ::: "memory")
#define CP_WAIT2()  asm volatile("cp.async.wait_group 2;\n" ::: "memory")

__device__ __forceinline__ void ldm_x4(uint32_t* r, uint32_t addr) {
    asm volatile("ldmatrix.sync.aligned.m8n8.x4.shared.b16 {%0,%1,%2,%3}, [%4];"
                 : "=r"(r[0]), "=r"(r[1]), "=r"(r[2]), "=r"(r[3]) : "r"(addr));
}
__device__ __forceinline__ void ldm_x4t(uint32_t* r, uint32_t addr) {
    asm volatile("ldmatrix.sync.aligned.m8n8.x4.trans.shared.b16 {%0,%1,%2,%3}, [%4];"
                 : "=r"(r[0]), "=r"(r[1]), "=r"(r[2]), "=r"(r[3]) : "r"(addr));
}
__device__ __forceinline__ void mma16816(float* d, const uint32_t* a,
                                         uint32_t b0, uint32_t b1) {
    asm volatile(
        "mma.sync.aligned.m16n8k16.row.col.f32.bf16.bf16.f32 "
        "{%0,%1,%2,%3}, {%4,%5,%6,%7}, {%8,%9}, {%0,%1,%2,%3};"
        : "+f"(d[0]), "+f"(d[1]), "+f"(d[2]), "+f"(d[3])
        : "r"(a[0]), "r"(a[1]), "r"(a[2]), "r"(a[3]), "r"(b0), "r"(b1));
}
__device__ __forceinline__ void mma_s8(int* d, const uint32_t* a,
                                       uint32_t b0, uint32_t b1) {
    asm volatile(
        "mma.sync.aligned.m16n8k32.row.col.s32.s8.s8.s32 "
        "{%0,%1,%2,%3}, {%4,%5,%6,%7}, {%8,%9}, {%0,%1,%2,%3};"
        : "+r"(d[0]), "+r"(d[1]), "+r"(d[2]), "+r"(d[3])
        : "r"(a[0]), "r"(a[1]), "r"(a[2]), "r"(a[3]), "r"(b0), "r"(b1));
}
__device__ __forceinline__ uint32_t packbf(float lo, float hi) {
    uint32_t d;
    asm("cvt.rn.bf16x2.f32 %0, %1, %2;" : "=r"(d) : "f"(hi), "f"(lo));
    return d;
}
__device__ __forceinline__ float bf_lo(uint32_t u) { return __uint_as_float(u << 16); }
__device__ __forceinline__ float bf_hi(uint32_t u) { return __uint_as_float(u & 0xffff0000u); }
__device__ __forceinline__ float ex2(float x) {
    float y; asm("ex2.approx.f32 %0, %1;" : "=f"(y) : "f"(x)); return y;
}

// ---------------------------------------------------------------------------
// Row-wise two-level int8 quantization. cols fixed = 2048, 256 thr (8 elem ea).
// x ~= s * (q1 + q2/254), |err| <= s * 2^-9.
// ---------------------------------------------------------------------------
__global__ __launch_bounds__(256) void rowquant(
    const float* __restrict__ x, int8_t* __restrict__ q1,
    int8_t* __restrict__ q2, float* __restrict__ s)
{
    __shared__ float wmax[8];
    const int row = blockIdx.x, t = threadIdx.x;
    const float* xr = x + (size_t)row * 2048 + t * 8;
    float4 v0 = ((const float4*)xr)[0];
    float4 v1 = ((const float4*)xr)[1];
    float vv[8] = {v0.x, v0.y, v0.z, v0.w, v1.x, v1.y, v1.z, v1.w};
    float m = 0.f;
#pragma unroll
    for (int j = 0; j < 8; j++) m = fmaxf(m, fabsf(vv[j]));
#pragma unroll
    for (int o = 16; o; o >>= 1) m = fmaxf(m, __shfl_xor_sync(~0u, m, o));
    if ((t & 31) == 0) wmax[t >> 5] = m;
    __syncthreads();
    float mm = wmax[0];
#pragma unroll
    for (int i = 1; i < 8; i++) mm = fmaxf(mm, wmax[i]);
    mm = fmaxf(mm, 1e-20f);
    if (t == 0) s[row] = mm * (1.f / 127.f);
    const float inv = 127.f / mm;

    uint32_t p1[2] = {0, 0}, p2[2] = {0, 0};
#pragma unroll
    for (int j = 0; j < 8; j++) {
        float xs = vv[j] * inv;
        float qf = rintf(xs);
        float rf = rintf((xs - qf) * 254.f);
        int iq = (int)qf, ir = (int)rf;
        p1[j >> 2] |= (uint32_t)(iq & 0xff) << ((j & 3) * 8);
        p2[j >> 2] |= (uint32_t)(ir & 0xff) << ((j & 3) * 8);
    }
    ((uint32_t*)q1)[row * 512 + t * 2]     = p1[0];
    ((uint32_t*)q1)[row * 512 + t * 2 + 1] = p1[1];
    ((uint32_t*)q2)[row * 512 + t * 2]     = p2[0];
    ((uint32_t*)q2)[row * 512 + t * 2 + 1] = p2[1];
}

// ---------------------------------------------------------------------------
// Two-level int8 GEMM: C = sA_i*sB_j*(A1B1 + (A1B2+A2B1)/254) + bias.
// CTA 128x128, BK=64 int8, 8 warps (2m x 4n), warp tile 64x32, 3-stage.
// blockIdx.z selects among 3 (B, C) argument sets.
// ---------------------------------------------------------------------------
#define GK 2048
#define NCH8 32
#define SSTG 32768
#define GS8_SMEM (3 * SSTG)

struct GArgs {
    const int8_t *B1, *B2;
    const float* sB;
    const float* bias;
    __nv_bfloat16 *Ch, *Cl;
    float* C;
};

__device__ __forceinline__ void s8_load(
    const int8_t* __restrict__ A1, const int8_t* __restrict__ A2,
    const int8_t* __restrict__ B1, const int8_t* __restrict__ B2,
    int m0, int n0, int k0, uint32_t sb, int t)
{
#pragma unroll
    for (int i = 0; i < 2; i++) {
        int idx = t + i * 256, r = idx >> 2, c = idx & 3;
        uint32_t so = (uint32_t)(r * 64 + (((c ^ ((r >> 1) & 3))) << 4));
        size_t ga = (size_t)(m0 + r) * GK + k0 + c * 16;
        size_t gb = (size_t)(n0 + r) * GK + k0 + c * 16;
        cp_async16(sb +          so, A1 + ga);
        cp_async16(sb +  8192u + so, A2 + ga);
        cp_async16(sb + 16384u + so, B1 + gb);
        cp_async16(sb + 24576u + so, B2 + gb);
    }
}

template<bool SPLIT>
__global__ __launch_bounds__(256, 1) void gemm_s8(
    const int8_t* __restrict__ A1, const int8_t* __restrict__ A2,
    const float* __restrict__ sA, GArgs a0, GArgs a1, GArgs a2)
{
    extern __shared__ char smem[];
    const uint32_t sbase = smem_u32(smem);
    const GArgs ga = (blockIdx.z == 0) ? a0 : (blockIdx.z == 1) ? a1 : a2;
    const int t = threadIdx.x, lane = t & 31, wid = t >> 5;
    const int warp_m = wid >> 2, warp_n = wid & 3;
    const int m0 = blockIdx.y * 128;
    const int n0 = blockIdx.x * 128;

    int a_row[4], b_row[2];
    uint32_t a_sw[4], b_sw[2];
#pragma unroll
    for (int mt = 0; mt < 4; mt++) {
        a_row[mt] = warp_m * 64 + mt * 16 + (lane & 15);
        a_sw[mt]  = (uint32_t)((a_row[mt] >> 1) & 3);
    }
#pragma unroll
    for (int pt = 0; pt < 2; pt++) {
        b_row[pt] = warp_n * 32 + pt * 16 + (lane & 7) + ((lane >> 4) & 1) * 8;
        b_sw[pt]  = (uint32_t)((b_row[pt] >> 1) & 3);
    }
    const uint32_t a_ch = (uint32_t)(lane >> 4);
    const uint32_t b_ch = (uint32_t)((lane >> 3) & 1);

    int acc1[4][4][4], acc2[4][4][4];
#pragma unroll
    for (int i = 0; i < 4; i++)
#pragma unroll
        for (int j = 0; j < 4; j++)
#pragma unroll
            for (int q = 0; q < 4; q++) { acc1[i][j][q] = 0; acc2[i][j][q] = 0; }

    s8_load(A1, A2, ga.B1, ga.B2, m0, n0, 0,   sbase,            t); CP_COMMIT();
    s8_load(A1, A2, ga.B1, ga.B2, m0, n0, 64,  sbase + SSTG,     t); CP_COMMIT();
    s8_load(A1, A2, ga.B1, ga.B2, m0, n0, 128, sbase + 2 * SSTG, t); CP_COMMIT();

    uint32_t stg = 0;
    for (int ch = 0; ch < NCH8; ch++) {
        CP_WAIT2();
        __syncthreads();
        const uint32_t sb = sbase + stg * SSTG;

#pragma unroll
        for (int s = 0; s < 2; s++) {        // two k32 steps per 64B chunk
            uint32_t Af1[4][4], Af2[4][4];
            uint32_t Bf1[2][4], Bf2[2][4];
#pragma unroll
            for (int mt = 0; mt < 4; mt++) {
                uint32_t c = (uint32_t)(s * 2) + a_ch;
                uint32_t off = (uint32_t)(a_row[mt] * 64) + ((c ^ a_sw[mt]) << 4);
                ldm_x4(Af1[mt], sb + off);
                ldm_x4(Af2[mt], sb + 8192u + off);
            }
#pragma unroll
            for (int pt = 0; pt < 2; pt++) {
                uint32_t c = (uint32_t)(s * 2) + b_ch;
                uint32_t off = (uint32_t)(b_row[pt] * 64) + ((c ^ b_sw[pt]) << 4);
                ldm_x4(Bf1[pt], sb + 16384u + off);
                ldm_x4(Bf2[pt], sb + 24576u + off);
            }
#pragma unroll
            for (int mt = 0; mt < 4; mt++)
#pragma unroll
                for (int nt = 0; nt < 4; nt++) {
                    const int pt = nt >> 1, hl = (nt & 1) * 2;
                    mma_s8(acc1[mt][nt], Af1[mt], Bf1[pt][hl], Bf1[pt][hl+1]);
                    mma_s8(acc2[mt][nt], Af1[mt], Bf2[pt][hl], Bf2[pt][hl+1]);
                    mma_s8(acc2[mt][nt], Af2[mt], Bf1[pt][hl], Bf1[pt][hl+1]);
                }
        }
        __syncthreads();
        if (ch + 3 < NCH8)
            s8_load(A1, A2, ga.B1, ga.B2, m0, n0, (ch + 3) * 64,
                    sbase + stg * SSTG, t);
        CP_COMMIT();
        stg = (stg == 2) ? 0 : stg + 1;
    }

    const float R = 1.f / 254.f;
#pragma unroll
    for (int mt = 0; mt < 4; mt++) {
        const int r0 = m0 + warp_m * 64 + mt * 16 + (lane >> 2);
        const float sa0 = sA[r0], sa1 = sA[r0 + 8];
#pragma unroll
        for (int nt = 0; nt < 4; nt++) {
            const int cc = n0 + warp_n * 32 + nt * 8 + (lane & 3) * 2;
            const float sb0 = ga.sB[cc], sb1 = ga.sB[cc + 1];
            const float bx = ga.bias[cc], by = ga.bias[cc + 1];
            float v0 = ((float)acc1[mt][nt][0] + (float)acc2[mt][nt][0] * R) * (sa0 * sb0) + bx;
            float v1 = ((float)acc1[mt][nt][1] + (float)acc2[mt][nt][1] * R) * (sa0 * sb1) + by;
            float v2 = ((float)acc1[mt][nt][2] + (float)acc2[mt][nt][2] * R) * (sa1 * sb0) + bx;
            float v3 = ((float)acc1[mt][nt][3] + (float)acc2[mt][nt][3] * R) * (sa1 * sb1) + by;
            if (!SPLIT) {
                *(float2*)(ga.C + (size_t)r0 * GK + cc)       = make_float2(v0, v1);
                *(float2*)(ga.C + (size_t)(r0 + 8) * GK + cc) = make_float2(v2, v3);
            } else {
                uint32_t h0 = packbf(v0, v1);
                uint32_t l0 = packbf(v0 - bf_lo(h0), v1 - bf_hi(h0));
                uint32_t h1 = packbf(v2, v3);
                uint32_t l1 = packbf(v2 - bf_lo(h1), v3 - bf_hi(h1));
                *(uint32_t*)(ga.Ch + (size_t)r0 * GK + cc)       = h0;
                *(uint32_t*)(ga.Cl + (size_t)r0 * GK + cc)       = l0;
                *(uint32_t*)(ga.Ch + (size_t)(r0 + 8) * GK + cc) = h1;
                *(uint32_t*)(ga.Cl + (size_t)(r0 + 8) * GK + cc) = l1;
            }
        }
    }
}

// ---------------------------------------------------------------------------
// Flash attention (causal), HMMA split-bf16, Q register-resident.
// Writes fp32 attention output (quantized afterwards for the output GEMM).
// ---------------------------------------------------------------------------
#define FQT 256
#define FKT 64
#define FA_SMEM 65536

__global__ __launch_bounds__(256, 1) void flash_hmma(
    const __nv_bfloat16* __restrict__ Qh, const __nv_bfloat16* __restrict__ Ql,
    const __nv_bfloat16* __restrict__ Kh, const __nv_bfloat16* __restrict__ Kl,
    const __nv_bfloat16* __restrict__ Vh, const __nv_bfloat16* __restrict__ Vl,
    float* __restrict__ O)
{
    extern __shared__ char smem[];
    const uint32_t sb = smem_u32(smem);
    const int t = threadIdx.x, lane = t & 31, wid = t >> 5;
    const int qt = blockIdx.x, bh = blockIdx.y;
    const int b = bh >> 5, h = bh & 31;
    const int q0 = qt * FQT;
    const size_t qbase = ((size_t)b * S_ + q0) * E_ + h * D_;
    const size_t kbase = ((size_t)b * S_) * E_ + h * D_;

#pragma unroll
    for (int i = 0; i < 8; i++) {
        int idx = t + i * 256, r = idx >> 3, c = idx & 7;
        uint32_t so = (uint32_t)(r * 128 + (((c ^ (r & 7))) << 4));
        size_t g = qbase + (size_t)r * E_ + c * 8;
        cp_async16(sb +          so, Qh + g);
        cp_async16(sb + 32768u + so, Ql + g);
    }
    CP_COMMIT();
    CP_WAIT0();
    __syncthreads();

    uint32_t fQh[2][4][4], fQl[2][4][4];
#pragma unroll
    for (int mt = 0; mt < 2; mt++)
#pragma unroll
        for (int kc = 0; kc < 4; kc++) {
            int row = wid * 32 + mt * 16 + (lane & 15);
            uint32_t c = (uint32_t)(2 * kc) + (uint32_t)(lane >> 4);
            uint32_t off = (uint32_t)(row * 128) + ((c ^ (uint32_t)(row & 7)) << 4);
            ldm_x4(fQh[mt][kc], sb + off);
            ldm_x4(fQl[mt][kc], sb + 32768u + off);
        }
    __syncthreads();

    const int jmax = 4 * (qt + 1);
#pragma unroll
    for (int i = 0; i < 2; i++) {
        int idx = t + i * 256, r = idx >> 3, c = idx & 7;
        uint32_t so = (uint32_t)(r * 128 + (((c ^ (r & 7))) << 4));
        size_t g = kbase + (size_t)r * E_ + c * 8;
        cp_async16(sb +          so, Kh + g);
        cp_async16(sb +  8192u + so, Kl + g);
        cp_async16(sb + 16384u + so, Vh + g);
        cp_async16(sb + 24576u + so, Vl + g);
    }
    CP_COMMIT();

    float Oacc[2][8][4];
#pragma unroll
    for (int i = 0; i < 2; i++)
#pragma unroll
        for (int j = 0; j < 8; j++)
#pragma unroll
            for (int q = 0; q < 4; q++) Oacc[i][j][q] = 0.f;
    float m_i[2][2] = {{-1e30f, -1e30f}, {-1e30f, -1e30f}};
    float l_i[2][2] = {{0.f, 0.f}, {0.f, 0.f}};
    const float CEXP = SCALE_ * 1.4426950408889634f;

    for (int jt = 0; jt < jmax; jt++) {
        const int k0 = jt * FKT;
        __syncthreads();
        if (jt + 1 < jmax) {
            uint32_t st = (uint32_t)((jt + 1) & 1) * 32768u;
#pragma unroll
            for (int i = 0; i < 2; i++) {
                int idx = t + i * 256, r = idx >> 3, c = idx & 7;
                uint32_t so = (uint32_t)(r * 128 + (((c ^ (r & 7))) << 4));
                size_t g = kbase + (size_t)(k0 + FKT + r) * E_ + c * 8;
                cp_async16(sb + st +          so, Kh + g);
                cp_async16(sb + st +  8192u + so, Kl + g);
                cp_async16(sb + st + 16384u + so, Vh + g);
                cp_async16(sb + st + 24576u + so, Vl + g);
            }
        }
        CP_COMMIT();
        CP_WAIT1();
        __syncthreads();
        const uint32_t sKh = sb + (uint32_t)(jt & 1) * 32768u;
        const uint32_t sKl = sKh + 8192u;
        const uint32_t sVh = sKh + 16384u;
        const uint32_t sVl = sKh + 24576u;

        float sacc[2][8][4];
#pragma unroll
        for (int i = 0; i < 2; i++)
#pragma unroll
            for (int j = 0; j < 8; j++)
#pragma unroll
                for (int q = 0; q < 4; q++) sacc[i][j][q] = 0.f;

#pragma unroll
        for (int kc = 0; kc < 4; kc++) {
#pragma unroll
            for (int np = 0; np < 4; np++) {
                int row = np * 16 + (lane & 7) + ((lane >> 4) & 1) * 8;
                uint32_t c = (uint32_t)(2 * kc) + (uint32_t)((lane >> 3) & 1);
                uint32_t off = (uint32_t)(row * 128) + ((c ^ (uint32_t)(row & 7)) << 4);
                uint32_t bkh[4], bkl[4];
                ldm_x4(bkh, sKh + off);
                ldm_x4(bkl, sKl + off);
#pragma unroll
                for (int nt2 = 0; nt2 < 2; nt2++) {
                    const int snt = np * 2 + nt2;
#pragma unroll
                    for (int mt = 0; mt < 2; mt++) {
                        mma16816(sacc[mt][snt], fQh[mt][kc], bkh[nt2*2], bkh[nt2*2+1]);
                        mma16816(sacc[mt][snt], fQh[mt][kc], bkl[nt2*2], bkl[nt2*2+1]);
                        mma16816(sacc[mt][snt], fQl[mt][kc], bkh[nt2*2], bkh[nt2*2+1]);
                    }
                }
            }
        }

        if (k0 + FKT - 1 > q0) {
#pragma unroll
            for (int mt = 0; mt < 2; mt++)
#pragma unroll
                for (int nt = 0; nt < 8; nt++)
#pragma unroll
                    for (int e = 0; e < 4; e++) {
                        int qrow = q0 + wid * 32 + mt * 16 + (lane >> 2) + (e >> 1) * 8;
                        int kcol = k0 + nt * 8 + (lane & 3) * 2 + (e & 1);
                        if (kcol > qrow) sacc[mt][nt][e] = -1e30f;
                    }
        }

#pragma unroll
        for (int mt = 0; mt < 2; mt++)
#pragma unroll
            for (int rr = 0; rr < 2; rr++) {
                float mx = -1e30f;
#pragma unroll
                for (int nt = 0; nt < 8; nt++)
                    mx = fmaxf(mx, fmaxf(sacc[mt][nt][rr*2], sacc[mt][nt][rr*2+1]));
                mx = fmaxf(mx, __shfl_xor_sync(0xffffffffu, mx, 1));
                mx = fmaxf(mx, __shfl_xor_sync(0xffffffffu, mx, 2));
                const float m_new = fmaxf(m_i[mt][rr], mx);
                const float mC = m_new * CEXP;
                const float alpha = ex2(m_i[mt][rr] * CEXP - mC);
                float rs = 0.f;
#pragma unroll
                for (int nt = 0; nt < 8; nt++) {
                    float p0 = ex2(sacc[mt][nt][rr*2]   * CEXP - mC);
                    float p1 = ex2(sacc[mt][nt][rr*2+1] * CEXP - mC);
                    sacc[mt][nt][rr*2] = p0; sacc[mt][nt][rr*2+1] = p1;
                    rs += p0 + p1;
                }
                rs += __shfl_xor_sync(0xffffffffu, rs, 1);
                rs += __shfl_xor_sync(0xffffffffu, rs, 2);
                l_i[mt][rr] = l_i[mt][rr] * alpha + rs;
                m_i[mt][rr] = m_new;
#pragma unroll
                for (int nd = 0; nd < 8; nd++) {
                    Oacc[mt][nd][rr*2]   *= alpha;
                    Oacc[mt][nd][rr*2+1] *= alpha;
                }
            }

#pragma unroll
        for (int kc = 0; kc < 4; kc++) {
            uint32_t ph[2][4], pl[2][4];
#pragma unroll
            for (int mt = 0; mt < 2; mt++) {
                float p00 = sacc[mt][2*kc][0],   p01 = sacc[mt][2*kc][1];
                float p10 = sacc[mt][2*kc][2],   p11 = sacc[mt][2*kc][3];
                float p20 = sacc[mt][2*kc+1][0], p21 = sacc[mt][2*kc+1][1];
                float p30 = sacc[mt][2*kc+1][2], p31 = sacc[mt][2*kc+1][3];
                ph[mt][0] = packbf(p00, p01);
                ph[mt][1] = packbf(p10, p11);
                ph[mt][2] = packbf(p20, p21);
                ph[mt][3] = packbf(p30, p31);
                pl[mt][0] = packbf(p00 - bf_lo(ph[mt][0]), p01 - bf_hi(ph[mt][0]));
                pl[mt][1] = packbf(p10 - bf_lo(ph[mt][1]), p11 - bf_hi(ph[mt][1]));
                pl[mt][2] = packbf(p20 - bf_lo(ph[mt][2]), p21 - bf_hi(ph[mt][2]));
                pl[mt][3] = packbf(p30 - bf_lo(ph[mt][3]), p31 - bf_hi(ph[mt][3]));
            }
#pragma unroll
            for (int ndp = 0; ndp < 4; ndp++) {
                int row = kc * 16 + (lane & 7) + ((lane >> 3) & 1) * 8;
                uint32_t c = (uint32_t)(2 * ndp) + (uint32_t)(lane >> 4);
                uint32_t off = (uint32_t)(row * 128) + ((c ^ (uint32_t)(row & 7)) << 4);
                uint32_t bvh[4], bvl[4];
                ldm_x4t(bvh, sVh + off);
                ldm_x4t(bvl, sVl + off);
#pragma unroll
                for (int nt2 = 0; nt2 < 2; nt2++) {
                    const int nd = ndp * 2 + nt2;
#pragma unroll
                    for (int mt = 0; mt < 2; mt++) {
                        mma16816(Oacc[mt][nd], ph[mt], bvh[nt2*2], bvh[nt2*2+1]);
                        mma16816(Oacc[mt][nd], ph[mt], bvl[nt2*2], bvl[nt2*2+1]);
                        mma16816(Oacc[mt][nd], pl[mt], bvh[nt2*2], bvh[nt2*2+1]);
                    }
                }
            }
        }
    }

#pragma unroll
    for (int mt = 0; mt < 2; mt++)
#pragma unroll
        for (int rr = 0; rr < 2; rr++) {
            const int row = wid * 32 + mt * 16 + (lane >> 2) + rr * 8;
            const float inv = 1.f / l_i[mt][rr];
            const size_t rb = qbase + (size_t)row * E_ + (lane & 3) * 2;
#pragma unroll
            for (int nd = 0; nd < 8; nd++) {
                float v0 = Oacc[mt][nd][rr*2]   * inv;
                float v1 = Oacc[mt][nd][rr*2+1] * inv;
                *(float2*)(O + rb + nd * 8) = make_float2(v0, v1);
            }
        }
}

// ---------------------------------------------------------------------------
extern "C" void kernel_launch(void* const* d_in, const int* in_sizes, int n_in,
                              void* d_out, int out_size)
{
    const float* x  = (const float*)d_in[0];
    const float* Wq = (const float*)d_in[1];
    const float* bq = (const float*)d_in[2];
    const float* Wk = (const float*)d_in[3];
    const float* bk = (const float*)d_in[4];
    const float* Wv = (const float*)d_in[5];
    const float* bv = (const float*)d_in[6];
    const float* Wo = (const float*)d_in[7];
    const float* bo = (const float*)d_in[8];
    float* out = (float*)d_out;

    int8_t *x1, *x2, *a1, *a2;
    int8_t *wq1, *wq2, *wk1, *wk2, *wv1, *wv2, *wo1, *wo2;
    float *sx, *sa, *swq, *swk, *swv, *swo, *attn;
    __nv_bfloat16 *qh, *ql, *kh, *kl, *vh, *vl;
    cudaGetSymbolAddress((void**)&x1, g_x1);
    cudaGetSymbolAddress((void**)&x2, g_x2);
    cudaGetSymbolAddress((void**)&sx, g_sx);
    cudaGetSymbolAddress((void**)&a1, g_a1);
    cudaGetSymbolAddress((void**)&a2, g_a2);
    cudaGetSymbolAddress((void**)&sa, g_sa);
    cudaGetSymbolAddress((void**)&attn, g_attn);
    cudaGetSymbolAddress((void**)&wq1, g_wq1);
    cudaGetSymbolAddress((void**)&wq2, g_wq2);
    cudaGetSymbolAddress((void**)&swq, g_swq);
    cudaGetSymbolAddress((void**)&wk1, g_wk1);
    cudaGetSymbolAddress((void**)&wk2, g_wk2);
    cudaGetSymbolAddress((void**)&swk, g_swk);
    cudaGetSymbolAddress((void**)&wv1, g_wv1);
    cudaGetSymbolAddress((void**)&wv2, g_wv2);
    cudaGetSymbolAddress((void**)&swv, g_swv);
    cudaGetSymbolAddress((void**)&wo1, g_wo1);
    cudaGetSymbolAddress((void**)&wo2, g_wo2);
    cudaGetSymbolAddress((void**)&swo, g_swo);
    cudaGetSymbolAddress((void**)&qh, g_qh);
    cudaGetSymbolAddress((void**)&ql, g_ql);
    cudaGetSymbolAddress((void**)&kh, g_kh);
    cudaGetSymbolAddress((void**)&kl, g_kl);
    cudaGetSymbolAddress((void**)&vh, g_vh);
    cudaGetSymbolAddress((void**)&vl, g_vl);

    cudaFuncSetAttribute(gemm_s8<true>,
                         cudaFuncAttributeMaxDynamicSharedMemorySize, GS8_SMEM);
    cudaFuncSetAttribute(gemm_s8<false>,
                         cudaFuncAttributeMaxDynamicSharedMemorySize, GS8_SMEM);
    cudaFuncSetAttribute(flash_hmma,
                         cudaFuncAttributeMaxDynamicSharedMemorySize, FA_SMEM);

    rowquant<<<M_, 256>>>(x,  x1,  x2,  sx);
    rowquant<<<E_, 256>>>(Wq, wq1, wq2, swq);
    rowquant<<<E_, 256>>>(Wk, wk1, wk2, swk);
    rowquant<<<E_, 256>>>(Wv, wv1, wv2, swv);
    rowquant<<<E_, 256>>>(Wo, wo1, wo2, swo);

    GArgs aq{wq1, wq2, swq, bq, qh, ql, nullptr};
    GArgs ak{wk1, wk2, swk, bk, kh, kl, nullptr};
    GArgs av{wv1, wv2, swv, bv, vh, vl, nullptr};
    GArgs ao{wo1, wo2, swo, bo, nullptr, nullptr, out};

    dim3 gq(E_ / 128, M_ / 128, 3);   // (16, 32, 3)
    gemm_s8<true><<<gq, 256, GS8_SMEM>>>(x1, x2, sx, aq, ak, av);

    dim3 ga(S_ / FQT, B_ * H_);       // (8, 64)
    flash_hmma<<<ga, 256, FA_SMEM>>>(qh, ql, kh, kl, vh, vl, attn);

    rowquant<<<M_, 256>>>(attn, a1, a2, sa);

    dim3 go(E_ / 128, M_ / 128, 1);
    gemm_s8<false><<<go, 256, GS8_SMEM>>>(a1, a2, sa, ao, ao, ao);
}